// round 4
// baseline (speedup 1.0000x reference)
#include <cuda_runtime.h>
#include <cuda_fp16.h>
#include <cuda_bf16.h>

#define NN 100000
#define EE 3200000
#define IND 81
#define HID 64
#define LAT 32
#define BN_EPS 1e-5f
#define SCAN_BLK 1024

// Scratch (device globals; no allocation allowed)
__device__ __align__(128) __half2 g_half[NN * 32];   // fp16 Hs rows (64 feats = 32 half2)
__device__ float g_bufA[NN * HID];
__device__ float g_bufB[NN * HID];
__device__ float g_dis[NN];
__device__ int   g_cnt[NN];
__device__ int   g_rowptr[NN + 1];
__device__ int   g_cursor[NN + 1];
__device__ int   g_csr[EE];
__device__ int   g_bsums[(NN + SCAN_BLK - 1) / SCAN_BLK + 1];
__device__ float g_stats[128];   // sum[64], sumsq[64] -> scale[64], shift[64]

// ---------------------------------------------------------------------------
__device__ __forceinline__ bool edges_are_i64(const void* ei) {
    long long v0 = ((const long long*)ei)[0];
    return (v0 >= 0 && v0 < 1000000LL);
}
__device__ __forceinline__ int edge_at(const void* ei, bool is64, int i) {
    return is64 ? (int)((const long long*)ei)[i] : ((const int*)ei)[i];
}

// ---------------------------------------------------------------------------
__global__ void zero_cnt(int* cnt, int n) {
    int i = blockIdx.x * blockDim.x + threadIdx.x;
    if (i < n) cnt[i] = 0;
}

__global__ void hist_dst(const void* ei, int* cnt, int E) {
    int e = blockIdx.x * blockDim.x + threadIdx.x;
    if (e >= E) return;
    bool is64 = edges_are_i64(ei);
    int d = edge_at(ei, is64, E + e);
    atomicAdd(&cnt[d], 1);
}

__global__ void scan1(const int* __restrict__ cnt, int* __restrict__ rowptr,
                      int* __restrict__ bsums, int n) {
    __shared__ int s[SCAN_BLK];
    int t = threadIdx.x;
    int i = blockIdx.x * SCAN_BLK + t;
    int val = (i < n) ? cnt[i] : 0;
    s[t] = val;
    __syncthreads();
    for (int off = 1; off < SCAN_BLK; off <<= 1) {
        int x = (t >= off) ? s[t - off] : 0;
        __syncthreads();
        s[t] += x;
        __syncthreads();
    }
    if (i < n) rowptr[i + 1] = s[t];
    if (t == SCAN_BLK - 1) bsums[blockIdx.x] = s[t];
}

__global__ void scan2(int* bsums, int nb) {
    __shared__ int s[SCAN_BLK];
    int t = threadIdx.x;
    int v = (t < nb) ? bsums[t] : 0;
    s[t] = v;
    __syncthreads();
    for (int off = 1; off < SCAN_BLK; off <<= 1) {
        int x = (t >= off) ? s[t - off] : 0;
        __syncthreads();
        s[t] += x;
        __syncthreads();
    }
    if (t < nb) bsums[t] = s[t] - v;   // exclusive
}

// add block offsets, init cursor, dis = rsqrt(deg+1), zero stats
__global__ void scan3(int* __restrict__ rowptr, int* __restrict__ cursor,
                      const int* __restrict__ bsums, const int* __restrict__ cnt,
                      float* __restrict__ dis, float* __restrict__ stats, int n) {
    int i = blockIdx.x * blockDim.x + threadIdx.x;
    if (i == 0) { rowptr[0] = 0; cursor[0] = 0; }
    if (i < 128) stats[i] = 0.0f;
    if (i < n) {
        int v = rowptr[i + 1] + bsums[i / SCAN_BLK];
        rowptr[i + 1] = v;
        cursor[i + 1] = v;
        dis[i] = rsqrtf((float)(cnt[i] + 1));
    }
}

__global__ void scatter_csr(const void* ei, int* __restrict__ cursor,
                            int* __restrict__ csr, int E) {
    int e = blockIdx.x * blockDim.x + threadIdx.x;
    if (e >= E) return;
    bool is64 = edges_are_i64(ei);
    int s = edge_at(ei, is64, e);
    int d = edge_at(ei, is64, E + e);
    int pos = atomicAdd(&cursor[d], 1);
    csr[pos] = s;
}

// ---------------------------------------------------------------------------
// GEMM: Yh[N,64] = half((X[N,81] @ W[81,64]) * dis[n])
__global__ void gemm81_dis(const float* __restrict__ X, const float* __restrict__ W,
                           const float* __restrict__ dis, __half* __restrict__ Yh, int N) {
    __shared__ float Ws[IND * HID];
    __shared__ float Xs[16][IND];
    int tx = threadIdx.x;
    int ty = threadIdx.y;
    int tid = ty * 64 + tx;
    for (int i = tid; i < IND * HID; i += 256) Ws[i] = W[i];
    int n0 = blockIdx.x * 16;
    for (int i = tid; i < 16 * IND; i += 256) {
        int r = i / IND, c = i % IND;
        int n = n0 + r;
        Xs[r][c] = (n < N) ? X[n * IND + c] : 0.0f;
    }
    __syncthreads();
    float acc[4] = {0.f, 0.f, 0.f, 0.f};
    for (int k = 0; k < IND; ++k) {
        float w = Ws[k * HID + tx];
        #pragma unroll
        for (int r = 0; r < 4; ++r) acc[r] += Xs[ty * 4 + r][k] * w;
    }
    #pragma unroll
    for (int r = 0; r < 4; ++r) {
        int n = n0 + ty * 4 + r;
        if (n < N) Yh[n * HID + tx] = __float2half(acc[r] * __ldg(&dis[n]));
    }
}

// GEMM with fused BN+ReLU input: Yh = half((relu(bn(X)) @ W) * dis[n])
__global__ void gemm64_bn_dis(const float* __restrict__ X, const float* __restrict__ W,
                              const float* __restrict__ stats, const float* __restrict__ dis,
                              __half* __restrict__ Yh, int N) {
    __shared__ float Ws[HID * HID];
    __shared__ float Xs[16][HID];
    __shared__ float sc[64], sh[64];
    int tx = threadIdx.x;
    int ty = threadIdx.y;
    int tid = ty * 64 + tx;
    for (int i = tid; i < HID * HID; i += 256) Ws[i] = W[i];
    if (tid < 64) { sc[tid] = stats[tid]; sh[tid] = stats[64 + tid]; }
    int n0 = blockIdx.x * 16;
    __syncthreads();
    for (int i = tid; i < 16 * HID; i += 256) {
        int r = i >> 6, c = i & 63;
        int n = n0 + r;
        float raw = (n < N) ? X[n * HID + c] : 0.0f;
        Xs[r][c] = fmaxf(fmaf(raw, sc[c], sh[c]), 0.0f);
    }
    __syncthreads();
    float acc[4] = {0.f, 0.f, 0.f, 0.f};
    for (int k = 0; k < HID; ++k) {
        float w = Ws[k * HID + tx];
        #pragma unroll
        for (int r = 0; r < 4; ++r) acc[r] += Xs[ty * 4 + r][k] * w;
    }
    #pragma unroll
    for (int r = 0; r < 4; ++r) {
        int n = n0 + ty * 4 + r;
        if (n < N) Yh[n * HID + tx] = __float2half(acc[r] * __ldg(&dis[n]));
    }
}

// Final heads
__global__ void gemm_mu_ls(const float* __restrict__ X,
                           const float* __restrict__ Wmu, const float* __restrict__ bmu,
                           const float* __restrict__ Wls, const float* __restrict__ bls,
                           float* __restrict__ out, int N) {
    __shared__ float Ws[HID * 64];
    __shared__ float bs[64];
    __shared__ float Xs[16][HID];
    int tx = threadIdx.x;
    int ty = threadIdx.y;
    int tid = ty * 64 + tx;
    for (int i = tid; i < HID * 64; i += 256) {
        int k = i >> 6, f = i & 63;
        Ws[i] = (f < LAT) ? Wmu[k * LAT + f] : Wls[k * LAT + (f - LAT)];
    }
    if (tid < 64) bs[tid] = (tid < LAT) ? bmu[tid] : bls[tid - LAT];
    int n0 = blockIdx.x * 16;
    for (int i = tid; i < 16 * HID; i += 256) {
        int r = i >> 6, c = i & 63;
        int n = n0 + r;
        Xs[r][c] = (n < N) ? X[n * HID + c] : 0.0f;
    }
    __syncthreads();
    float acc[4] = {0.f, 0.f, 0.f, 0.f};
    for (int k = 0; k < HID; ++k) {
        float w = Ws[k * 64 + tx];
        #pragma unroll
        for (int r = 0; r < 4; ++r) acc[r] += Xs[ty * 4 + r][k] * w;
    }
    int f = tx & (LAT - 1);
    long long off = (tx < LAT) ? 0 : (long long)N * LAT;
    #pragma unroll
    for (int r = 0; r < 4; ++r) {
        int n = n0 + ty * 4 + r;
        if (n < N) out[off + (long long)n * LAT + f] = acc[r] + bs[tx];
    }
}

// ---------------------------------------------------------------------------
// Aggregation: out[n] = (sum_{s in nbr(n)} Hs[s] + Hs[n]) * dis[n] + b
// Unroll-4 with 4 independent accumulator chains. Optional fused BN stats:
// per-block reduction of sum / sumsq into global stats via atomics.
__global__ void aggregate_h(const __half2* __restrict__ Hh, const int* __restrict__ rowptr,
                            const int* __restrict__ csr, const float* __restrict__ dis,
                            const float* __restrict__ bias, float2* __restrict__ out2,
                            float* __restrict__ stats, int N) {
    int n = (blockIdx.x * blockDim.x + threadIdx.x) >> 5;
    int lane = threadIdx.x & 31;
    int wid = (threadIdx.x >> 5);       // 0..7
    bool active = (n < N);

    float ox = 0.f, oy = 0.f;
    if (active) {
        int base = n * 32 + lane;
        float2 a0 = __half22float2(__ldg(&Hh[base]));   // self term
        float2 a1 = make_float2(0.f, 0.f);
        float2 a2 = make_float2(0.f, 0.f);
        float2 a3 = make_float2(0.f, 0.f);
        int j = __ldg(&rowptr[n]);
        int end = __ldg(&rowptr[n + 1]);
        for (; j + 4 <= end; j += 4) {
            int s0 = __ldg(&csr[j]);
            int s1 = __ldg(&csr[j + 1]);
            int s2 = __ldg(&csr[j + 2]);
            int s3 = __ldg(&csr[j + 3]);
            float2 v0 = __half22float2(__ldg(&Hh[s0 * 32 + lane]));
            float2 v1 = __half22float2(__ldg(&Hh[s1 * 32 + lane]));
            float2 v2 = __half22float2(__ldg(&Hh[s2 * 32 + lane]));
            float2 v3 = __half22float2(__ldg(&Hh[s3 * 32 + lane]));
            a0.x += v0.x; a0.y += v0.y;
            a1.x += v1.x; a1.y += v1.y;
            a2.x += v2.x; a2.y += v2.y;
            a3.x += v3.x; a3.y += v3.y;
        }
        for (; j < end; ++j) {
            int s0 = __ldg(&csr[j]);
            float2 v0 = __half22float2(__ldg(&Hh[s0 * 32 + lane]));
            a0.x += v0.x; a0.y += v0.y;
        }
        float dd = __ldg(&dis[n]);
        float bx = 0.f, by = 0.f;
        if (bias) { float2 b = ((const float2*)bias)[lane]; bx = b.x; by = b.y; }
        ox = fmaf(a0.x + a1.x + a2.x + a3.x, dd, bx);
        oy = fmaf(a0.y + a1.y + a2.y + a3.y, dd, by);
        out2[n * 32 + lane] = make_float2(ox, oy);
    }

    if (stats) {
        // Block BN-stat reduction: 8 warps (nodes) x 32 lanes x 2 feats.
        __shared__ float2 sv[8][32];
        __shared__ float2 sq[8][32];
        sv[wid][lane] = make_float2(ox, oy);
        sq[wid][lane] = make_float2(ox * ox, oy * oy);
        __syncthreads();
        int tid = threadIdx.x;
        if (tid < 64) {
            int l = tid & 31;
            bool doSq = (tid >= 32);
            float sx = 0.f, sy = 0.f;
            #pragma unroll
            for (int w = 0; w < 8; ++w) {
                float2 v = doSq ? sq[w][l] : sv[w][l];
                sx += v.x; sy += v.y;
            }
            int off = doSq ? 64 : 0;
            atomicAdd(&stats[off + 2 * l], sx);
            atomicAdd(&stats[off + 2 * l + 1], sy);
        }
    }
}

// ---------------------------------------------------------------------------
__global__ void bn_finalize(float* stats, const float* __restrict__ g,
                            const float* __restrict__ beta, int N) {
    int f = threadIdx.x;
    if (f >= 64) return;
    float invN = 1.0f / (float)N;
    float m = stats[f] * invN;
    float v = stats[64 + f] * invN - m * m;
    float scale = g[f] * rsqrtf(v + BN_EPS);
    stats[f] = scale;
    stats[64 + f] = beta[f] - m * scale;
}

__global__ void zero_stats(float* stats) {
    int i = threadIdx.x;
    if (i < 128) stats[i] = 0.0f;
}

// Hs[n,f] = half(relu(bn(B[n,f])) * dis[n])
__global__ void bn_relu_dis(const float* __restrict__ H, const float* __restrict__ stats,
                            const float* __restrict__ dis, __half* __restrict__ out, int total) {
    int idx = blockIdx.x * blockDim.x + threadIdx.x;
    if (idx >= total) return;
    int f = idx & 63;
    int n = idx >> 6;
    float y = fmaxf(fmaf(H[idx], stats[f], stats[64 + f]), 0.0f);
    out[idx] = __float2half(y * __ldg(&dis[n]));
}

// ---------------------------------------------------------------------------
extern "C" void kernel_launch(void* const* d_in, const int* in_sizes, int n_in,
                              void* d_out, int out_size) {
    const float* x    = (const float*)d_in[0];
    const void*  ei   = d_in[1];
    const float* W1   = (const float*)d_in[2];
    const float* b1   = (const float*)d_in[3];
    const float* g1   = (const float*)d_in[4];
    const float* be1  = (const float*)d_in[5];
    const float* W2   = (const float*)d_in[6];
    const float* b2   = (const float*)d_in[7];
    const float* g2   = (const float*)d_in[8];
    const float* be2  = (const float*)d_in[9];
    const float* Wmu  = (const float*)d_in[10];
    const float* bmu  = (const float*)d_in[11];
    const float* Wls  = (const float*)d_in[12];
    const float* bls  = (const float*)d_in[13];
    float* out = (float*)d_out;

    int N = in_sizes[0] / IND;
    int E = in_sizes[1] / 2;

    float *pA, *pB, *pDis, *pStats;
    __half2* pH;
    int *pCnt, *pRow, *pCur, *pCsr, *pBs;
    cudaGetSymbolAddress((void**)&pA, g_bufA);
    cudaGetSymbolAddress((void**)&pB, g_bufB);
    cudaGetSymbolAddress((void**)&pDis, g_dis);
    cudaGetSymbolAddress((void**)&pStats, g_stats);
    cudaGetSymbolAddress((void**)&pH, g_half);
    cudaGetSymbolAddress((void**)&pCnt, g_cnt);
    cudaGetSymbolAddress((void**)&pRow, g_rowptr);
    cudaGetSymbolAddress((void**)&pCur, g_cursor);
    cudaGetSymbolAddress((void**)&pCsr, g_csr);
    cudaGetSymbolAddress((void**)&pBs, g_bsums);

    int NH = N * HID;
    int nScanBlocks = (N + SCAN_BLK - 1) / SCAN_BLK;
    dim3 gThr(64, 4);
    int gemmGrid = (N + 15) / 16;
    int aggGrid = (N * 32 + 255) / 256;

    // 1. CSR build + normalization (stats zeroed in scan3)
    zero_cnt<<<(N + 255) / 256, 256>>>(pCnt, N);
    hist_dst<<<(E + 255) / 256, 256>>>(ei, pCnt, E);
    scan1<<<nScanBlocks, SCAN_BLK>>>(pCnt, pRow, pBs, N);
    scan2<<<1, SCAN_BLK>>>(pBs, nScanBlocks);
    scan3<<<(N + 255) / 256, 256>>>(pRow, pCur, pBs, pCnt, pDis, pStats, N);
    scatter_csr<<<(E + 255) / 256, 256>>>(ei, pCur, pCsr, E);

    // 2. conv1 (+ fused BN1 stats)
    gemm81_dis<<<gemmGrid, gThr>>>(x, W1, pDis, (__half*)pH, N);
    aggregate_h<<<aggGrid, 256>>>(pH, pRow, pCsr, pDis, b1, (float2*)pB, pStats, N);
    bn_finalize<<<1, 64>>>(pStats, g1, be1, N);

    // 3. conv2 (BN1 apply fused into GEMM input; fused BN2 stats in aggregate)
    gemm64_bn_dis<<<gemmGrid, gThr>>>(pB, W2, pStats, pDis, (__half*)pH, N);
    zero_stats<<<1, 128>>>(pStats);  // safe: gemm64 consumed stats already (serial stream)
    aggregate_h<<<aggGrid, 256>>>(pH, pRow, pCsr, pDis, b2, (float2*)pA, pStats, N);
    bn_finalize<<<1, 64>>>(pStats, g2, be2, N);

    // 4. Hs = relu(bn(A)) * dis ; shared aggregation for both heads
    bn_relu_dis<<<(NH + 255) / 256, 256>>>(pA, pStats, pDis, (__half*)pH, NH);
    aggregate_h<<<aggGrid, 256>>>(pH, pRow, pCsr, pDis, (const float*)nullptr, (float2*)pB,
                                  (float*)nullptr, N);

    // 5. heads
    gemm_mu_ls<<<gemmGrid, gThr>>>(pB, Wmu, bmu, Wls, bls, out, N);
}

// round 5
// speedup vs baseline: 1.4912x; 1.4912x over previous
#include <cuda_runtime.h>
#include <cuda_fp16.h>
#include <cuda_bf16.h>

#define NN 100000
#define EE 3200000
#define IND 81
#define HID 64
#define LAT 32
#define BN_EPS 1e-5f
#define SCAN_BLK 1024

// Scratch (device globals; no allocation allowed)
__device__ __align__(128) __half2 g_half[NN * 32];   // fp16 Hs rows (64 feats = 32 half2)
__device__ float g_bufA[NN * HID];
__device__ float g_bufB[NN * HID];
__device__ float g_dis[NN];
__device__ int   g_cnt[NN];
__device__ int   g_rowptr[NN + 1];
__device__ int   g_cursor[NN + 1];
__device__ int   g_csr[EE];
__device__ int   g_bsums[(NN + SCAN_BLK - 1) / SCAN_BLK + 1];
__device__ float g_stats[128];   // sum[64], sumsq[64] -> scale[64], shift[64]

// ---------------------------------------------------------------------------
__device__ __forceinline__ bool edges_are_i64(const void* ei) {
    long long v0 = ((const long long*)ei)[0];
    return (v0 >= 0 && v0 < 1000000LL);
}
__device__ __forceinline__ int edge_at(const void* ei, bool is64, int i) {
    return is64 ? (int)((const long long*)ei)[i] : ((const int*)ei)[i];
}

// ---------------------------------------------------------------------------
__global__ void zero_cnt(int* cnt, int n) {
    int i = blockIdx.x * blockDim.x + threadIdx.x;
    if (i < n) cnt[i] = 0;
}

__global__ void hist_dst(const void* ei, int* cnt, int E) {
    int e = blockIdx.x * blockDim.x + threadIdx.x;
    if (e >= E) return;
    bool is64 = edges_are_i64(ei);
    int d = edge_at(ei, is64, E + e);
    atomicAdd(&cnt[d], 1);
}

__global__ void scan1(const int* __restrict__ cnt, int* __restrict__ rowptr,
                      int* __restrict__ bsums, int n) {
    __shared__ int s[SCAN_BLK];
    int t = threadIdx.x;
    int i = blockIdx.x * SCAN_BLK + t;
    int val = (i < n) ? cnt[i] : 0;
    s[t] = val;
    __syncthreads();
    for (int off = 1; off < SCAN_BLK; off <<= 1) {
        int x = (t >= off) ? s[t - off] : 0;
        __syncthreads();
        s[t] += x;
        __syncthreads();
    }
    if (i < n) rowptr[i + 1] = s[t];
    if (t == SCAN_BLK - 1) bsums[blockIdx.x] = s[t];
}

__global__ void scan2(int* bsums, int nb) {
    __shared__ int s[SCAN_BLK];
    int t = threadIdx.x;
    int v = (t < nb) ? bsums[t] : 0;
    s[t] = v;
    __syncthreads();
    for (int off = 1; off < SCAN_BLK; off <<= 1) {
        int x = (t >= off) ? s[t - off] : 0;
        __syncthreads();
        s[t] += x;
        __syncthreads();
    }
    if (t < nb) bsums[t] = s[t] - v;   // exclusive
}

// add block offsets, init cursor, dis = rsqrt(deg+1)
__global__ void scan3(int* __restrict__ rowptr, int* __restrict__ cursor,
                      const int* __restrict__ bsums, const int* __restrict__ cnt,
                      float* __restrict__ dis, int n) {
    int i = blockIdx.x * blockDim.x + threadIdx.x;
    if (i == 0) { rowptr[0] = 0; cursor[0] = 0; }
    if (i < n) {
        int v = rowptr[i + 1] + bsums[i / SCAN_BLK];
        rowptr[i + 1] = v;
        cursor[i + 1] = v;
        dis[i] = rsqrtf((float)(cnt[i] + 1));
    }
}

__global__ void scatter_csr(const void* ei, int* __restrict__ cursor,
                            int* __restrict__ csr, int E) {
    int e = blockIdx.x * blockDim.x + threadIdx.x;
    if (e >= E) return;
    bool is64 = edges_are_i64(ei);
    int s = edge_at(ei, is64, e);
    int d = edge_at(ei, is64, E + e);
    int pos = atomicAdd(&cursor[d], 1);
    csr[pos] = s;
}

// ---------------------------------------------------------------------------
// GEMM: Yh[N,64] = half((X[N,81] @ W[81,64]) * dis[n])
__global__ void gemm81_dis(const float* __restrict__ X, const float* __restrict__ W,
                           const float* __restrict__ dis, __half* __restrict__ Yh, int N) {
    __shared__ float Ws[IND * HID];
    __shared__ float Xs[16][IND];
    int tx = threadIdx.x;
    int ty = threadIdx.y;
    int tid = ty * 64 + tx;
    for (int i = tid; i < IND * HID; i += 256) Ws[i] = W[i];
    int n0 = blockIdx.x * 16;
    for (int i = tid; i < 16 * IND; i += 256) {
        int r = i / IND, c = i % IND;
        int n = n0 + r;
        Xs[r][c] = (n < N) ? X[n * IND + c] : 0.0f;
    }
    __syncthreads();
    float acc[4] = {0.f, 0.f, 0.f, 0.f};
    for (int k = 0; k < IND; ++k) {
        float w = Ws[k * HID + tx];
        #pragma unroll
        for (int r = 0; r < 4; ++r) acc[r] += Xs[ty * 4 + r][k] * w;
    }
    #pragma unroll
    for (int r = 0; r < 4; ++r) {
        int n = n0 + ty * 4 + r;
        if (n < N) Yh[n * HID + tx] = __float2half(acc[r] * __ldg(&dis[n]));
    }
}

// GEMM with fused BN+ReLU input: Yh = half((relu(bn(X)) @ W) * dis[n])
__global__ void gemm64_bn_dis(const float* __restrict__ X, const float* __restrict__ W,
                              const float* __restrict__ stats, const float* __restrict__ dis,
                              __half* __restrict__ Yh, int N) {
    __shared__ float Ws[HID * HID];
    __shared__ float Xs[16][HID];
    __shared__ float sc[64], sh[64];
    int tx = threadIdx.x;
    int ty = threadIdx.y;
    int tid = ty * 64 + tx;
    for (int i = tid; i < HID * HID; i += 256) Ws[i] = W[i];
    if (tid < 64) { sc[tid] = stats[tid]; sh[tid] = stats[64 + tid]; }
    int n0 = blockIdx.x * 16;
    __syncthreads();
    for (int i = tid; i < 16 * HID; i += 256) {
        int r = i >> 6, c = i & 63;
        int n = n0 + r;
        float raw = (n < N) ? X[n * HID + c] : 0.0f;
        Xs[r][c] = fmaxf(fmaf(raw, sc[c], sh[c]), 0.0f);
    }
    __syncthreads();
    float acc[4] = {0.f, 0.f, 0.f, 0.f};
    for (int k = 0; k < HID; ++k) {
        float w = Ws[k * HID + tx];
        #pragma unroll
        for (int r = 0; r < 4; ++r) acc[r] += Xs[ty * 4 + r][k] * w;
    }
    #pragma unroll
    for (int r = 0; r < 4; ++r) {
        int n = n0 + ty * 4 + r;
        if (n < N) Yh[n * HID + tx] = __float2half(acc[r] * __ldg(&dis[n]));
    }
}

// Final heads
__global__ void gemm_mu_ls(const float* __restrict__ X,
                           const float* __restrict__ Wmu, const float* __restrict__ bmu,
                           const float* __restrict__ Wls, const float* __restrict__ bls,
                           float* __restrict__ out, int N) {
    __shared__ float Ws[HID * 64];
    __shared__ float bs[64];
    __shared__ float Xs[16][HID];
    int tx = threadIdx.x;
    int ty = threadIdx.y;
    int tid = ty * 64 + tx;
    for (int i = tid; i < HID * 64; i += 256) {
        int k = i >> 6, f = i & 63;
        Ws[i] = (f < LAT) ? Wmu[k * LAT + f] : Wls[k * LAT + (f - LAT)];
    }
    if (tid < 64) bs[tid] = (tid < LAT) ? bmu[tid] : bls[tid - LAT];
    int n0 = blockIdx.x * 16;
    for (int i = tid; i < 16 * HID; i += 256) {
        int r = i >> 6, c = i & 63;
        int n = n0 + r;
        Xs[r][c] = (n < N) ? X[n * HID + c] : 0.0f;
    }
    __syncthreads();
    float acc[4] = {0.f, 0.f, 0.f, 0.f};
    for (int k = 0; k < HID; ++k) {
        float w = Ws[k * 64 + tx];
        #pragma unroll
        for (int r = 0; r < 4; ++r) acc[r] += Xs[ty * 4 + r][k] * w;
    }
    int f = tx & (LAT - 1);
    long long off = (tx < LAT) ? 0 : (long long)N * LAT;
    #pragma unroll
    for (int r = 0; r < 4; ++r) {
        int n = n0 + ty * 4 + r;
        if (n < N) out[off + (long long)n * LAT + f] = acc[r] + bs[tx];
    }
}

// ---------------------------------------------------------------------------
// Aggregation, 2 nodes per warp: lanes 0-15 -> node 2w, lanes 16-31 -> node 2w+1.
// Each lane loads 8 B (uint2 = 2 half2 = 4 feats); one warp LDG covers 2 rows.
// out[n] = (sum_{s in nbr(n)} Hs[s] + Hs[n]) * dis[n] + b
__global__ void aggregate_h2(const __half2* __restrict__ Hh, const int* __restrict__ rowptr,
                             const int* __restrict__ csr, const float* __restrict__ dis,
                             const float* __restrict__ bias, float4* __restrict__ out4, int N) {
    int warp = (blockIdx.x * blockDim.x + threadIdx.x) >> 5;
    int lane = threadIdx.x & 31;
    int grp = lane >> 4;           // 0 or 1
    int sub = lane & 15;           // 0..15: handles feats 4*sub..4*sub+3
    int n = warp * 2 + grp;
    if (n >= N) return;

    const uint2* Hr = (const uint2*)Hh;   // 16 uint2 per row
    uint2 raw = __ldg(&Hr[n * 16 + sub]);
    __half2 h0 = *reinterpret_cast<__half2*>(&raw.x);
    __half2 h1 = *reinterpret_cast<__half2*>(&raw.y);
    float2 p0 = __half22float2(h0), p1 = __half22float2(h1);
    // two independent accumulator chains (unroll-2)
    float ax0 = p0.x, ay0 = p0.y, az0 = p1.x, aw0 = p1.y;
    float ax1 = 0.f, ay1 = 0.f, az1 = 0.f, aw1 = 0.f;

    int j = __ldg(&rowptr[n]);
    int end = __ldg(&rowptr[n + 1]);
    for (; j + 2 <= end; j += 2) {
        int s0 = __ldg(&csr[j]);
        int s1 = __ldg(&csr[j + 1]);
        uint2 r0 = __ldg(&Hr[s0 * 16 + sub]);
        uint2 r1 = __ldg(&Hr[s1 * 16 + sub]);
        float2 v00 = __half22float2(*reinterpret_cast<__half2*>(&r0.x));
        float2 v01 = __half22float2(*reinterpret_cast<__half2*>(&r0.y));
        float2 v10 = __half22float2(*reinterpret_cast<__half2*>(&r1.x));
        float2 v11 = __half22float2(*reinterpret_cast<__half2*>(&r1.y));
        ax0 += v00.x; ay0 += v00.y; az0 += v01.x; aw0 += v01.y;
        ax1 += v10.x; ay1 += v10.y; az1 += v11.x; aw1 += v11.y;
    }
    if (j < end) {
        int s0 = __ldg(&csr[j]);
        uint2 r0 = __ldg(&Hr[s0 * 16 + sub]);
        float2 v00 = __half22float2(*reinterpret_cast<__half2*>(&r0.x));
        float2 v01 = __half22float2(*reinterpret_cast<__half2*>(&r0.y));
        ax0 += v00.x; ay0 += v00.y; az0 += v01.x; aw0 += v01.y;
    }

    float dd = __ldg(&dis[n]);
    float4 bb = make_float4(0.f, 0.f, 0.f, 0.f);
    if (bias) bb = ((const float4*)bias)[sub];
    out4[n * 16 + sub] = make_float4(fmaf(ax0 + ax1, dd, bb.x),
                                     fmaf(ay0 + ay1, dd, bb.y),
                                     fmaf(az0 + az1, dd, bb.z),
                                     fmaf(aw0 + aw1, dd, bb.w));
}

// ---------------------------------------------------------------------------
// BatchNorm (separate full-pass stats, as in the 416us version)
__global__ void zero_stats(float* stats) {
    int i = threadIdx.x;
    if (i < 128) stats[i] = 0.0f;
}

__global__ void bn_stats(const float* __restrict__ H, float* stats, int N) {
    int tid = threadIdx.x;
    int col = tid & 63;
    int r = blockIdx.x * 4 + (tid >> 6);
    int rstride = gridDim.x * 4;
    float s = 0.0f, q = 0.0f;
    for (; r < N; r += rstride) {
        float v = H[r * HID + col];
        s += v; q += v * v;
    }
    __shared__ float sh[256], qh[256];
    sh[tid] = s; qh[tid] = q;
    __syncthreads();
    if (tid < 64) {
        float S = sh[tid] + sh[tid + 64] + sh[tid + 128] + sh[tid + 192];
        float Q = qh[tid] + qh[tid + 64] + qh[tid + 128] + qh[tid + 192];
        atomicAdd(&stats[tid], S);
        atomicAdd(&stats[64 + tid], Q);
    }
}

__global__ void bn_finalize(float* stats, const float* __restrict__ g,
                            const float* __restrict__ beta, int N) {
    int f = threadIdx.x;
    if (f >= 64) return;
    float invN = 1.0f / (float)N;
    float m = stats[f] * invN;
    float v = stats[64 + f] * invN - m * m;
    float scale = g[f] * rsqrtf(v + BN_EPS);
    stats[f] = scale;
    stats[64 + f] = beta[f] - m * scale;
}

// Hs[n,f] = half(relu(bn(B[n,f])) * dis[n])
__global__ void bn_relu_dis(const float* __restrict__ H, const float* __restrict__ stats,
                            const float* __restrict__ dis, __half* __restrict__ out, int total) {
    int idx = blockIdx.x * blockDim.x + threadIdx.x;
    if (idx >= total) return;
    int f = idx & 63;
    int n = idx >> 6;
    float y = fmaxf(fmaf(H[idx], stats[f], stats[64 + f]), 0.0f);
    out[idx] = __float2half(y * __ldg(&dis[n]));
}

// ---------------------------------------------------------------------------
extern "C" void kernel_launch(void* const* d_in, const int* in_sizes, int n_in,
                              void* d_out, int out_size) {
    const float* x    = (const float*)d_in[0];
    const void*  ei   = d_in[1];
    const float* W1   = (const float*)d_in[2];
    const float* b1   = (const float*)d_in[3];
    const float* g1   = (const float*)d_in[4];
    const float* be1  = (const float*)d_in[5];
    const float* W2   = (const float*)d_in[6];
    const float* b2   = (const float*)d_in[7];
    const float* g2   = (const float*)d_in[8];
    const float* be2  = (const float*)d_in[9];
    const float* Wmu  = (const float*)d_in[10];
    const float* bmu  = (const float*)d_in[11];
    const float* Wls  = (const float*)d_in[12];
    const float* bls  = (const float*)d_in[13];
    float* out = (float*)d_out;

    int N = in_sizes[0] / IND;
    int E = in_sizes[1] / 2;

    float *pA, *pB, *pDis, *pStats;
    __half2* pH;
    int *pCnt, *pRow, *pCur, *pCsr, *pBs;
    cudaGetSymbolAddress((void**)&pA, g_bufA);
    cudaGetSymbolAddress((void**)&pB, g_bufB);
    cudaGetSymbolAddress((void**)&pDis, g_dis);
    cudaGetSymbolAddress((void**)&pStats, g_stats);
    cudaGetSymbolAddress((void**)&pH, g_half);
    cudaGetSymbolAddress((void**)&pCnt, g_cnt);
    cudaGetSymbolAddress((void**)&pRow, g_rowptr);
    cudaGetSymbolAddress((void**)&pCur, g_cursor);
    cudaGetSymbolAddress((void**)&pCsr, g_csr);
    cudaGetSymbolAddress((void**)&pBs, g_bsums);

    int NH = N * HID;
    int nScanBlocks = (N + SCAN_BLK - 1) / SCAN_BLK;
    dim3 gThr(64, 4);
    int gemmGrid = (N + 15) / 16;
    int aggGrid = ((N + 1) / 2 * 32 + 255) / 256;   // 2 nodes per warp, 8 warps/block

    // 1. CSR build + normalization
    zero_cnt<<<(N + 255) / 256, 256>>>(pCnt, N);
    hist_dst<<<(E + 255) / 256, 256>>>(ei, pCnt, E);
    scan1<<<nScanBlocks, SCAN_BLK>>>(pCnt, pRow, pBs, N);
    scan2<<<1, SCAN_BLK>>>(pBs, nScanBlocks);
    scan3<<<(N + 255) / 256, 256>>>(pRow, pCur, pBs, pCnt, pDis, N);
    scatter_csr<<<(E + 255) / 256, 256>>>(ei, pCur, pCsr, E);

    // 2. conv1
    gemm81_dis<<<gemmGrid, gThr>>>(x, W1, pDis, (__half*)pH, N);
    aggregate_h2<<<aggGrid, 256>>>(pH, pRow, pCsr, pDis, b1, (float4*)pB, N);

    // 3. BN1 stats
    zero_stats<<<1, 128>>>(pStats);
    bn_stats<<<512, 256>>>(pB, pStats, N);
    bn_finalize<<<1, 64>>>(pStats, g1, be1, N);

    // 4. conv2 (BN1 apply fused into GEMM input)
    gemm64_bn_dis<<<gemmGrid, gThr>>>(pB, W2, pStats, pDis, (__half*)pH, N);
    aggregate_h2<<<aggGrid, 256>>>(pH, pRow, pCsr, pDis, b2, (float4*)pA, N);

    // 5. BN2 stats
    zero_stats<<<1, 128>>>(pStats);
    bn_stats<<<512, 256>>>(pA, pStats, N);
    bn_finalize<<<1, 64>>>(pStats, g2, be2, N);

    // 6. Hs = relu(bn(A)) * dis ; shared aggregation for both heads
    bn_relu_dis<<<(NH + 255) / 256, 256>>>(pA, pStats, pDis, (__half*)pH, NH);
    aggregate_h2<<<aggGrid, 256>>>(pH, pRow, pCsr, pDis, (const float*)nullptr, (float4*)pB, N);

    // 7. heads
    gemm_mu_ls<<<gemmGrid, gThr>>>(pB, Wmu, bmu, Wls, bls, out, N);
}